// round 4
// baseline (speedup 1.0000x reference)
#include <cuda_runtime.h>
#include <stdint.h>

#define NUSERS 50000
#define NITEMS 30000
#define NNODES 80000
#define EK 64
#define HH 32
#define NNZADJ 2000000
#define NNZR 1000000

// ---------------- scratch (device globals; allocation is forbidden) ----------------
__device__ float g_itf[2][NITEMS * EK];
__device__ float g_ihl[2][NITEMS * HH];
__device__ float g_uhl[2][NUSERS * HH];
__device__ float g_ih[2][NITEMS * HH];
__device__ float g_uh[2][NUSERS * HH];
__device__ float g_e0[NNODES * EK];      // cge
__device__ float g_e1[NNODES * EK];
__device__ float g_e2[NNODES * EK];
__device__ float g_m0[2][NUSERS * EK];
__device__ float g_m1[2][NNODES * EK];
__device__ float g_lat[2][HH * EK];

// ---------------- threefry2x32 (JAX-compatible, 20 rounds) ----------------
__host__ __device__ __forceinline__ void tf2x32(uint32_t k0, uint32_t k1,
                                                uint32_t x0, uint32_t x1,
                                                uint32_t* o0, uint32_t* o1) {
  uint32_t ks2 = k0 ^ k1 ^ 0x1BD11BDAu;
  uint32_t v0 = x0 + k0, v1 = x1 + k1;
#define TFR(r) { v0 += v1; v1 = (v1 << (r)) | (v1 >> (32 - (r))); v1 ^= v0; }
  TFR(13) TFR(15) TFR(26) TFR(6)
  v0 += k1;  v1 += ks2 + 1u;
  TFR(17) TFR(29) TFR(16) TFR(24)
  v0 += ks2; v1 += k0 + 2u;
  TFR(13) TFR(15) TFR(26) TFR(6)
  v0 += k0;  v1 += k1 + 3u;
  TFR(17) TFR(29) TFR(16) TFR(24)
  v0 += k1;  v1 += ks2 + 4u;
  TFR(13) TFR(15) TFR(26) TFR(6)
  v0 += ks2; v1 += k0 + 5u;
#undef TFR
  *o0 = v0; *o1 = v1;
}

// ---------------- vector atomic add ----------------
__device__ __forceinline__ void red_add_f4(float4* p, float4 v) {
  asm volatile("red.global.add.v4.f32 [%0], {%1,%2,%3,%4};"
               :: "l"(p), "f"(v.x), "f"(v.y), "f"(v.z), "f"(v.w) : "memory");
}
__device__ __forceinline__ float4 scale4(float s, float4 v) {
  return make_float4(s * v.x, s * v.y, s * v.z, s * v.w);
}

// ---------------- SpMM: edge-per-thread, y pre-zeroed ----------------
template <int C4>
__global__ void spmm_edge(const int* __restrict__ rows, const int* __restrict__ cols,
                          const float* __restrict__ vals, const float4* __restrict__ x,
                          float4* __restrict__ y, int nnz) {
  int e = blockIdx.x * 256 + threadIdx.x;
  if (e >= nnz) return;
  int r = __ldg(rows + e), c = __ldg(cols + e);
  float v = __ldg(vals + e);
  const float4* xr = x + (size_t)c * C4;
  float4* yr = y + (size_t)r * C4;
  float4 xv[C4];
#pragma unroll
  for (int i = 0; i < C4; i++) xv[i] = __ldg(xr + i);
#pragma unroll
  for (int i = 0; i < C4; i++) red_add_f4(yr + i, scale4(v, xv[i]));
}

// both-modality r-spmm: blockIdx.y selects modality
template <int C4>
__global__ void spmm_r_both(const int* __restrict__ rows, const int* __restrict__ cols,
                            const float* __restrict__ vals,
                            const float4* __restrict__ x0, const float4* __restrict__ x1,
                            float4* __restrict__ y0, float4* __restrict__ y1, int nnz) {
  int e = blockIdx.x * 256 + threadIdx.x;
  if (e >= nnz) return;
  const float4* x = blockIdx.y ? x1 : x0;
  float4* y = blockIdx.y ? y1 : y0;
  int r = __ldg(rows + e), c = __ldg(cols + e);
  float v = __ldg(vals + e);
  const float4* xr = x + (size_t)c * C4;
  float4* yr = y + (size_t)r * C4;
  float4 xv[C4];
#pragma unroll
  for (int i = 0; i < C4; i++) xv[i] = __ldg(xr + i);
#pragma unroll
  for (int i = 0; i < C4; i++) red_add_f4(yr + i, scale4(v, xv[i]));
}

// first cge spmm: gather virtually from concat(Gu, Gi)
__global__ void spmm_cge1(const int* __restrict__ rows, const int* __restrict__ cols,
                          const float* __restrict__ vals, const float4* __restrict__ Gu,
                          const float4* __restrict__ Gi, float4* __restrict__ y, int nnz) {
  int e = blockIdx.x * 256 + threadIdx.x;
  if (e >= nnz) return;
  int r = __ldg(rows + e), c = __ldg(cols + e);
  float v = __ldg(vals + e);
  const float4* xr = (c < NUSERS) ? Gu + (size_t)c * 16 : Gi + (size_t)(c - NUSERS) * 16;
  float4* yr = y + (size_t)r * 16;
  float4 xv[16];
#pragma unroll
  for (int i = 0; i < 16; i++) xv[i] = __ldg(xr + i);
#pragma unroll
  for (int i = 0; i < 16; i++) red_add_f4(yr + i, scale4(v, xv[i]));
}

// mge adj spmm, both modalities; gathers from (m0users*inv | itf)
__global__ void spmm_mge_both(const int* __restrict__ rows, const int* __restrict__ cols,
                              const float* __restrict__ vals,
                              const float4* __restrict__ m0A, const float4* __restrict__ m0B,
                              const float4* __restrict__ itfA, const float4* __restrict__ itfB,
                              const float* __restrict__ inv,
                              float4* __restrict__ y0, float4* __restrict__ y1, int nnz) {
  int e = blockIdx.x * 256 + threadIdx.x;
  if (e >= nnz) return;
  const float4* m0  = blockIdx.y ? m0B : m0A;
  const float4* itf = blockIdx.y ? itfB : itfA;
  float4* y = blockIdx.y ? y1 : y0;
  int r = __ldg(rows + e), c = __ldg(cols + e);
  float v = __ldg(vals + e);
  const float4* xr;
  if (c < NUSERS) { xr = m0 + (size_t)c * 16; v *= __ldg(inv + c); }
  else            { xr = itf + (size_t)(c - NUSERS) * 16; }
  float4* yr = y + (size_t)r * 16;
  float4 xv[16];
#pragma unroll
  for (int i = 0; i < 16; i++) xv[i] = __ldg(xr + i);
#pragma unroll
  for (int i = 0; i < 16; i++) red_add_f4(yr + i, scale4(v, xv[i]));
}

// ---------------- fused GEMM both modalities (reg double-buffered) ----------------
// blockIdx.y: 0 = visual, 1 = text. Cf = A@Bt [64 cols], Cl = A@Bh [32 cols].
__global__ __launch_bounds__(256, 2)
void gemm_both_kernel(const float* __restrict__ A0, const float* __restrict__ A1,
                      const float* __restrict__ Bt0, const float* __restrict__ Bt1,
                      const float* __restrict__ Bh0, const float* __restrict__ Bh1,
                      float* __restrict__ Cf0, float* __restrict__ Cf1,
                      float* __restrict__ Cl0, float* __restrict__ Cl1,
                      int F0, int F1) {
  __shared__ float As[32][129];
  __shared__ float Bs[32][97];
  const int mmod = blockIdx.y;
  const float* A  = mmod ? A1 : A0;
  const float* Bt = mmod ? Bt1 : Bt0;
  const float* Bh = mmod ? Bh1 : Bh0;
  float* Cf = mmod ? Cf1 : Cf0;
  float* Cl = mmod ? Cl1 : Cl0;
  const int F = mmod ? F1 : F0;

  const int row0 = blockIdx.x * 128;
  const int tid = threadIdx.x;
  const int tx = tid & 15, ty = tid >> 4;
  const int lr = tid >> 1;            // load row 0..127
  const int lk = (tid & 1) * 16;      // load k offset
  const int gr_l = row0 + lr;
  const bool rok = gr_l < NITEMS;
  const float* Arow = A + (size_t)gr_l * F + lk;

  float4 a4[4];
  float bb[12];
  const float4 z4 = make_float4(0.f, 0.f, 0.f, 0.f);
#pragma unroll
  for (int i = 0; i < 4; i++) a4[i] = rok ? __ldg((const float4*)(Arow + 4 * i)) : z4;
#pragma unroll
  for (int i = 0; i < 12; i++) {
    int idx = tid + 256 * i, kk = idx / 96, c = idx - kk * 96;
    bb[i] = (c < 64) ? __ldg(Bt + kk * 64 + c) : __ldg(Bh + kk * 32 + (c - 64));
  }

  float acc[8][6];
#pragma unroll
  for (int i = 0; i < 8; i++)
#pragma unroll
    for (int j = 0; j < 6; j++) acc[i][j] = 0.0f;

  for (int k0 = 0; k0 < F; k0 += 32) {
#pragma unroll
    for (int i = 0; i < 4; i++) {
      As[lk + 4 * i + 0][lr] = a4[i].x;
      As[lk + 4 * i + 1][lr] = a4[i].y;
      As[lk + 4 * i + 2][lr] = a4[i].z;
      As[lk + 4 * i + 3][lr] = a4[i].w;
    }
#pragma unroll
    for (int i = 0; i < 12; i++) {
      int idx = tid + 256 * i, kk = idx / 96, c = idx - kk * 96;
      Bs[kk][c] = bb[i];
    }
    __syncthreads();
    int kn = k0 + 32;
    if (kn < F) {
#pragma unroll
      for (int i = 0; i < 4; i++) a4[i] = rok ? __ldg((const float4*)(Arow + kn + 4 * i)) : z4;
#pragma unroll
      for (int i = 0; i < 12; i++) {
        int idx = tid + 256 * i, kk = idx / 96, c = idx - kk * 96;
        bb[i] = (c < 64) ? __ldg(Bt + (kn + kk) * 64 + c) : __ldg(Bh + (kn + kk) * 32 + (c - 64));
      }
    }
#pragma unroll 8
    for (int kk = 0; kk < 32; kk++) {
      float a[8], b[6];
#pragma unroll
      for (int i = 0; i < 8; i++) a[i] = As[kk][ty * 8 + i];
#pragma unroll
      for (int j = 0; j < 6; j++) b[j] = Bs[kk][tx * 6 + j];
#pragma unroll
      for (int i = 0; i < 8; i++)
#pragma unroll
        for (int j = 0; j < 6; j++) acc[i][j] = fmaf(a[i], b[j], acc[i][j]);
    }
    __syncthreads();
  }
#pragma unroll
  for (int i = 0; i < 8; i++) {
    int gr = row0 + ty * 8 + i;
    if (gr < NITEMS) {
#pragma unroll
      for (int j = 0; j < 6; j++) {
        int c = tx * 6 + j;
        if (c < 64) Cf[gr * 64 + c] = acc[i][j];
        else        Cl[gr * 32 + (c - 64)] = acc[i][j];
      }
    }
  }
}

// ---------------- gumbel softmax both modalities, warp per row ----------------
__global__ void gumbel_both_kernel(const float* __restrict__ lg0, const float* __restrict__ lg1,
                                   float* __restrict__ o0, float* __restrict__ o1, int rows,
                                   unsigned k00, unsigned k01, unsigned k10, unsigned k11) {
  int row = blockIdx.x * 8 + (threadIdx.x >> 5);
  if (row >= rows) return;
  const float* logits = blockIdx.y ? lg1 : lg0;
  float* out = blockIdx.y ? o1 : o0;
  unsigned k0 = blockIdx.y ? k10 : k00;
  unsigned k1 = blockIdx.y ? k11 : k01;
  int lane = threadIdx.x & 31;
  unsigned idx = (unsigned)row * 32u + (unsigned)lane;
  unsigned b0, b1;
  tf2x32(k0, k1, 0u, idx, &b0, &b1);
  unsigned bits = b0 ^ b1;
  float f = __uint_as_float((bits >> 9) | 0x3f800000u) - 1.0f;
  const float TINY = 1.1754943508222875e-38f;
  float u = fmaxf(TINY, f + TINY);
  float g = -logf(-logf(u));
  float z = (logits[row * 32 + lane] + g) * 5.0f;   // /tau, tau=0.2
  float mx = z;
#pragma unroll
  for (int s = 16; s; s >>= 1) mx = fmaxf(mx, __shfl_xor_sync(0xffffffffu, mx, s));
  float e = expf(z - mx);
  float sm = e;
#pragma unroll
  for (int s = 16; s; s >>= 1) sm += __shfl_xor_sync(0xffffffffu, sm, s);
  out[row * 32 + lane] = e / sm;
}

// ---------------- cge combine: cge = (concat(Gu,Gi) + e1 + e2)/3 ----------------
__global__ void cge_combine_kernel(const float* __restrict__ Gu, const float* __restrict__ Gi,
                                   const float* __restrict__ e1, const float* __restrict__ e2,
                                   float* __restrict__ cge) {
  int idx = blockIdx.x * 256 + threadIdx.x;
  if (idx >= NNODES * EK) return;
  float ego = (idx < NUSERS * EK) ? Gu[idx] : Gi[idx - NUSERS * EK];
  cge[idx] = (ego + e1[idx] + e2[idx]) * (1.0f / 3.0f);
}

// ---------------- lat[32,64] += ih^T @ icge, both modalities (lat pre-zeroed) ----------------
__global__ void lat_both_kernel(const float* __restrict__ w0, const float* __restrict__ w1,
                                const float* __restrict__ icge,
                                float* __restrict__ lat0, float* __restrict__ lat1, int chunk) {
  const float* w = blockIdx.y ? w1 : w0;
  float* lat = blockIdx.y ? lat1 : lat0;
  int lane = threadIdx.x & 31;
  int kg = threadIdx.x >> 5;  // 0..7
  int start = blockIdx.x * chunk;
  int end = min(start + chunk, NITEMS);
  float acc[8] = {0, 0, 0, 0, 0, 0, 0, 0};
  for (int it = start; it < end; ++it) {
    float wv = w[it * HH + lane];
    const float* cr = icge + it * EK + kg * 8;
#pragma unroll
    for (int j = 0; j < 8; j++) acc[j] = fmaf(wv, __ldg(cr + j), acc[j]);
  }
#pragma unroll
  for (int j = 0; j < 8; j++) atomicAdd(&lat[lane * EK + kg * 8 + j], acc[j]);
}

// ---------------- hyper apply, all 4 outputs in one launch ----------------
// blockIdx.y: modality. blockIdx.x < IBLK: items; else users.
#define IBLK ((NITEMS * EK + 255) / 256)
#define UBLK ((NUSERS * EK + 255) / 256)
__global__ void hyper_apply_all(const float* __restrict__ ih0, const float* __restrict__ ih1,
                                const float* __restrict__ uh0, const float* __restrict__ uh1,
                                const float* __restrict__ lat0, const float* __restrict__ lat1,
                                float* __restrict__ outIV, float* __restrict__ outIT,
                                float* __restrict__ outUV, float* __restrict__ outUT) {
  __shared__ float sl[HH * EK];
  const float* lat = blockIdx.y ? lat1 : lat0;
  for (int t = threadIdx.x; t < HH * EK; t += 256) sl[t] = lat[t];
  __syncthreads();
  const float* w;
  float* out;
  int idx;
  if (blockIdx.x < IBLK) {
    w = blockIdx.y ? ih1 : ih0;
    out = blockIdx.y ? outIT : outIV;
    idx = blockIdx.x * 256 + threadIdx.x;
    if (idx >= NITEMS * EK) return;
  } else {
    w = blockIdx.y ? uh1 : uh0;
    out = blockIdx.y ? outUT : outUV;
    idx = (blockIdx.x - IBLK) * 256 + threadIdx.x;
    if (idx >= NUSERS * EK) return;
  }
  int r = idx >> 6, k = idx & 63;
  float s = 0.0f;
#pragma unroll
  for (int h = 0; h < HH; h++) s = fmaf(w[r * HH + h], sl[h * EK + k], s);
  out[idx] = s;
}

// ---------------- final: out = cge + l2n(m1a) + l2n(m1b) + 0.2*l2n(ghe) ----------------
__global__ void final_kernel(float* __restrict__ out, const float* __restrict__ cge,
                             const float* __restrict__ m1a, const float* __restrict__ m1b) {
  const int OI   = NUSERS * EK;
  const int OHVU = (NUSERS + NITEMS) * EK;
  const int OHVI = OHVU + NUSERS * EK;
  const int OHTU = OHVI + NITEMS * EK;
  const int OHTI = OHTU + NUSERS * EK;
  int row = blockIdx.x * 8 + (threadIdx.x >> 5);
  if (row >= NNODES) return;
  int lane = threadIdx.x & 31;
  const float* hv;
  const float* ht;
  float* dst;
  if (row < NUSERS) {
    hv = out + OHVU + row * EK; ht = out + OHTU + row * EK; dst = out + row * EK;
  } else {
    int ir = row - NUSERS;
    hv = out + OHVI + ir * EK;  ht = out + OHTI + ir * EK;  dst = out + OI + ir * EK;
  }
  int b = row * EK;
  float a0 = m1a[b + lane], a1 = m1a[b + lane + 32];
  float c0 = m1b[b + lane], c1 = m1b[b + lane + 32];
  float g0 = hv[lane] + ht[lane];
  float g1 = hv[lane + 32] + ht[lane + 32];
  float sa = a0 * a0 + a1 * a1;
  float sc = c0 * c0 + c1 * c1;
  float sg = g0 * g0 + g1 * g1;
#pragma unroll
  for (int s = 16; s; s >>= 1) {
    sa += __shfl_xor_sync(0xffffffffu, sa, s);
    sc += __shfl_xor_sync(0xffffffffu, sc, s);
    sg += __shfl_xor_sync(0xffffffffu, sg, s);
  }
  float ia = 1.0f / fmaxf(sqrtf(sa), 1e-12f);
  float ic = 1.0f / fmaxf(sqrtf(sc), 1e-12f);
  float ig = 0.2f / fmaxf(sqrtf(sg), 1e-12f);
  dst[lane]      = cge[b + lane]      + a0 * ia + c0 * ic + g0 * ig;
  dst[lane + 32] = cge[b + lane + 32] + a1 * ia + c1 * ic + g1 * ig;
}

// ================================================================================
extern "C" void kernel_launch(void* const* d_in, const int* in_sizes, int n_in,
                              void* d_out, int out_size) {
  const float* Gu       = (const float*)d_in[0];
  const float* Gi       = (const float*)d_in[1];
  const float* feat_v   = (const float*)d_in[2];
  const float* feat_t   = (const float*)d_in[3];
  const float* trs_v    = (const float*)d_in[4];
  const float* trs_t    = (const float*)d_in[5];
  const float* hyp_v    = (const float*)d_in[6];
  const float* hyp_t    = (const float*)d_in[7];
  const float* inv      = (const float*)d_in[8];
  const float* adj_vals = (const float*)d_in[9];
  const float* r_vals   = (const float*)d_in[10];
  const int*   adj_rows = (const int*)d_in[11];
  const int*   adj_cols = (const int*)d_in[12];
  const int*   r_rows   = (const int*)d_in[13];
  const int*   r_cols   = (const int*)d_in[14];
  float* out = (float*)d_out;
  int Fv = in_sizes[2] / NITEMS;
  int Ft = in_sizes[3] / NITEMS;

  float *p_itf, *p_ihl, *p_uhl, *p_ih, *p_uh, *p_e0, *p_e1, *p_e2, *p_m0, *p_m1, *p_lat;
  cudaGetSymbolAddress((void**)&p_itf, g_itf);
  cudaGetSymbolAddress((void**)&p_ihl, g_ihl);
  cudaGetSymbolAddress((void**)&p_uhl, g_uhl);
  cudaGetSymbolAddress((void**)&p_ih,  g_ih);
  cudaGetSymbolAddress((void**)&p_uh,  g_uh);
  cudaGetSymbolAddress((void**)&p_e0,  g_e0);
  cudaGetSymbolAddress((void**)&p_e1,  g_e1);
  cudaGetSymbolAddress((void**)&p_e2,  g_e2);
  cudaGetSymbolAddress((void**)&p_m0,  g_m0);
  cudaGetSymbolAddress((void**)&p_m1,  g_m1);
  cudaGetSymbolAddress((void**)&p_lat, g_lat);
  float* p_itfT = p_itf + NITEMS * EK;
  float* p_ihlT = p_ihl + NITEMS * HH;
  float* p_uhlT = p_uhl + NUSERS * HH;
  float* p_ihT  = p_ih + NITEMS * HH;
  float* p_uhT  = p_uh + NUSERS * HH;
  float* p_m0T  = p_m0 + NUSERS * EK;
  float* p_m1T  = p_m1 + NNODES * EK;
  float* p_latT = p_lat + HH * EK;

  // JAX threefry keys (host arithmetic; deterministic)
  uint32_t ki0[2], ki1[2], ku0[2], ku1[2];
  for (int m = 0; m < 2; m++) {
    uint32_t km0, km1;
    tf2x32(0u, 42u, 0u, (uint32_t)m, &km0, &km1);   // fold_in(key(42), m)
    tf2x32(km0, km1, 0u, 0u, &ki0[m], &ki1[m]);     // split -> k1 (i_hyper)
    tf2x32(km0, km1, 0u, 1u, &ku0[m], &ku1[m]);     // split -> k2 (u_hyper)
  }

  const size_t NB  = (size_t)NNODES * EK * sizeof(float);
  const size_t UB  = (size_t)NUSERS * EK * sizeof(float);
  const size_t UHB = (size_t)NUSERS * HH * sizeof(float);
  const int GADJ = (NNZADJ + 255) / 256;
  const int GR   = (NNZR + 255) / 256;
  const int GN   = (NNODES * EK + 255) / 256;
  const int OHVU = (NUSERS + NITEMS) * EK;
  const int OHVI = OHVU + NUSERS * EK;
  const int OHTU = OHVI + NITEMS * EK;
  const int OHTI = OHTU + NUSERS * EK;

  // ---- all scratch zeroing up front ----
  cudaMemsetAsync(p_e1, 0, NB, 0);
  cudaMemsetAsync(p_e2, 0, NB, 0);
  cudaMemsetAsync(p_uhl, 0, 2 * UHB, 0);
  cudaMemsetAsync(p_m0, 0, 2 * UB, 0);
  cudaMemsetAsync(p_m1, 0, 2 * NB, 0);
  cudaMemsetAsync(p_lat, 0, 2 * HH * EK * sizeof(float), 0);

  // ---- both GEMMs in one launch ----
  gemm_both_kernel<<<dim3((NITEMS + 127) / 128, 2), 256>>>(
      feat_v, feat_t, trs_v, trs_t, hyp_v, hyp_t,
      p_itf, p_itfT, p_ihl, p_ihlT, Fv, Ft);

  // ---- cge chain ----
  spmm_cge1<<<GADJ, 256>>>(adj_rows, adj_cols, adj_vals,
                           (const float4*)Gu, (const float4*)Gi, (float4*)p_e1, NNZADJ);
  spmm_edge<16><<<GADJ, 256>>>(adj_rows, adj_cols, adj_vals,
                               (const float4*)p_e1, (float4*)p_e2, NNZADJ);
  cge_combine_kernel<<<GN, 256>>>(Gu, Gi, p_e1, p_e2, p_e0);

  // ---- gumbel (items) both modalities ----
  gumbel_both_kernel<<<dim3((NITEMS + 7) / 8, 2), 256>>>(
      p_ihl, p_ihlT, p_ih, p_ihT, NITEMS, ki0[0], ki1[0], ki0[1], ki1[1]);

  // ---- r-spmms, both modalities ----
  spmm_r_both<8><<<dim3(GR, 2), 256>>>(r_rows, r_cols, r_vals,
                                       (const float4*)p_ihl, (const float4*)p_ihlT,
                                       (float4*)p_uhl, (float4*)p_uhlT, NNZR);
  gumbel_both_kernel<<<dim3((NUSERS + 7) / 8, 2), 256>>>(
      p_uhl, p_uhlT, p_uh, p_uhT, NUSERS, ku0[0], ku1[0], ku0[1], ku1[1]);
  spmm_r_both<16><<<dim3(GR, 2), 256>>>(r_rows, r_cols, r_vals,
                                        (const float4*)p_itf, (const float4*)p_itfT,
                                        (float4*)p_m0, (float4*)p_m0T, NNZR);

  // ---- mge adj spmm, both modalities ----
  spmm_mge_both<<<dim3(GADJ, 2), 256>>>(adj_rows, adj_cols, adj_vals,
                                        (const float4*)p_m0, (const float4*)p_m0T,
                                        (const float4*)p_itf, (const float4*)p_itfT,
                                        inv, (float4*)p_m1, (float4*)p_m1T, NNZADJ);

  // ---- hyper path ----
  lat_both_kernel<<<dim3(120, 2), 256>>>(p_ih, p_ihT, p_e0 + NUSERS * EK, p_lat, p_latT, 250);
  hyper_apply_all<<<dim3(IBLK + UBLK, 2), 256>>>(
      p_ih, p_ihT, p_uh, p_uhT, p_lat, p_latT,
      out + OHVI, out + OHTI, out + OHVU, out + OHTU);

  final_kernel<<<(NNODES + 7) / 8, 256>>>(out, p_e0, p_m1, p_m1T);
}

// round 5
// speedup vs baseline: 1.4985x; 1.4985x over previous
#include <cuda_runtime.h>
#include <stdint.h>

#define NUSERS 50000
#define NITEMS 30000
#define NNODES 80000
#define EK 64
#define HH 32
#define NNZADJ 2000000
#define NNZR 1000000

// ---------------- scratch (device globals; allocation is forbidden) ----------------
__device__ float g_itf[2][NITEMS * EK];
__device__ float g_ihl[2][NITEMS * HH];
__device__ float g_uhl[2][NUSERS * HH];
__device__ float g_ih[2][NITEMS * HH];
__device__ float g_uh[2][NUSERS * HH];
__device__ float g_e0[NNODES * EK];      // cge
__device__ float g_e1[NNODES * EK];
__device__ float g_e2[NNODES * EK];
__device__ float g_m0[2][NUSERS * EK];
__device__ float g_m1[2][NNODES * EK];
__device__ float g_lat[2][HH * EK];

// ---------------- threefry2x32 (JAX-compatible, 20 rounds) ----------------
__host__ __device__ __forceinline__ void tf2x32(uint32_t k0, uint32_t k1,
                                                uint32_t x0, uint32_t x1,
                                                uint32_t* o0, uint32_t* o1) {
  uint32_t ks2 = k0 ^ k1 ^ 0x1BD11BDAu;
  uint32_t v0 = x0 + k0, v1 = x1 + k1;
#define TFR(r) { v0 += v1; v1 = (v1 << (r)) | (v1 >> (32 - (r))); v1 ^= v0; }
  TFR(13) TFR(15) TFR(26) TFR(6)
  v0 += k1;  v1 += ks2 + 1u;
  TFR(17) TFR(29) TFR(16) TFR(24)
  v0 += ks2; v1 += k0 + 2u;
  TFR(13) TFR(15) TFR(26) TFR(6)
  v0 += k0;  v1 += k1 + 3u;
  TFR(17) TFR(29) TFR(16) TFR(24)
  v0 += k1;  v1 += ks2 + 4u;
  TFR(13) TFR(15) TFR(26) TFR(6)
  v0 += ks2; v1 += k0 + 5u;
#undef TFR
  *o0 = v0; *o1 = v1;
}

// ---------------- vector atomic add ----------------
__device__ __forceinline__ void red_add_f4(float4* p, float4 v) {
  asm volatile("red.global.add.v4.f32 [%0], {%1,%2,%3,%4};"
               :: "l"(p), "f"(v.x), "f"(v.y), "f"(v.z), "f"(v.w) : "memory");
}

// ---------------- SpMM: (edge,col4)-per-thread (coalesced), y pre-zeroed ----------------
template <int C4>
__global__ void spmm_kernel(const int* __restrict__ rows, const int* __restrict__ cols,
                            const float* __restrict__ vals, const float4* __restrict__ x,
                            float4* __restrict__ y, int nnz) {
  int idx = blockIdx.x * 256 + threadIdx.x;
  if (idx >= nnz * C4) return;
  int e = idx / C4;
  int c = idx - e * C4;
  int r = __ldg(rows + e), cl = __ldg(cols + e);
  float v = __ldg(vals + e);
  float4 xv = __ldg(x + (size_t)cl * C4 + c);
  red_add_f4(y + (size_t)r * C4 + c, make_float4(v * xv.x, v * xv.y, v * xv.z, v * xv.w));
}

// both-modality r-spmm: blockIdx.y selects modality
template <int C4>
__global__ void spmm_r_both(const int* __restrict__ rows, const int* __restrict__ cols,
                            const float* __restrict__ vals,
                            const float4* __restrict__ x0, const float4* __restrict__ x1,
                            float4* __restrict__ y0, float4* __restrict__ y1, int nnz) {
  int idx = blockIdx.x * 256 + threadIdx.x;
  if (idx >= nnz * C4) return;
  const float4* x = blockIdx.y ? x1 : x0;
  float4* y = blockIdx.y ? y1 : y0;
  int e = idx / C4;
  int c = idx - e * C4;
  int r = __ldg(rows + e), cl = __ldg(cols + e);
  float v = __ldg(vals + e);
  float4 xv = __ldg(x + (size_t)cl * C4 + c);
  red_add_f4(y + (size_t)r * C4 + c, make_float4(v * xv.x, v * xv.y, v * xv.z, v * xv.w));
}

// first cge spmm: gather virtually from concat(Gu, Gi)
__global__ void spmm_cge1(const int* __restrict__ rows, const int* __restrict__ cols,
                          const float* __restrict__ vals, const float4* __restrict__ Gu,
                          const float4* __restrict__ Gi, float4* __restrict__ y, int nnz) {
  int idx = blockIdx.x * 256 + threadIdx.x;
  if (idx >= nnz * 16) return;
  int e = idx >> 4;
  int c = idx & 15;
  int r = __ldg(rows + e), cl = __ldg(cols + e);
  float v = __ldg(vals + e);
  const float4* xr = (cl < NUSERS) ? Gu + (size_t)cl * 16 : Gi + (size_t)(cl - NUSERS) * 16;
  float4 xv = __ldg(xr + c);
  red_add_f4(y + (size_t)r * 16 + c, make_float4(v * xv.x, v * xv.y, v * xv.z, v * xv.w));
}

// mge adj spmm, both modalities; gathers from (m0users*inv | itf)
__global__ void spmm_mge_both(const int* __restrict__ rows, const int* __restrict__ cols,
                              const float* __restrict__ vals,
                              const float4* __restrict__ m0A, const float4* __restrict__ m0B,
                              const float4* __restrict__ itfA, const float4* __restrict__ itfB,
                              const float* __restrict__ inv,
                              float4* __restrict__ y0, float4* __restrict__ y1, int nnz) {
  int idx = blockIdx.x * 256 + threadIdx.x;
  if (idx >= nnz * 16) return;
  const float4* m0  = blockIdx.y ? m0B : m0A;
  const float4* itf = blockIdx.y ? itfB : itfA;
  float4* y = blockIdx.y ? y1 : y0;
  int e = idx >> 4;
  int c = idx & 15;
  int r = __ldg(rows + e), cl = __ldg(cols + e);
  float v = __ldg(vals + e);
  const float4* xr;
  if (cl < NUSERS) { xr = m0 + (size_t)cl * 16; v *= __ldg(inv + cl); }
  else             { xr = itf + (size_t)(cl - NUSERS) * 16; }
  float4 xv = __ldg(xr + c);
  red_add_f4(y + (size_t)r * 16 + c, make_float4(v * xv.x, v * xv.y, v * xv.z, v * xv.w));
}

// ---------------- fused GEMM both modalities (reg double-buffered) ----------------
// blockIdx.y: 0 = visual, 1 = text. Cf = A@Bt [64 cols], Cl = A@Bh [32 cols].
__global__ __launch_bounds__(256, 2)
void gemm_both_kernel(const float* __restrict__ A0, const float* __restrict__ A1,
                      const float* __restrict__ Bt0, const float* __restrict__ Bt1,
                      const float* __restrict__ Bh0, const float* __restrict__ Bh1,
                      float* __restrict__ Cf0, float* __restrict__ Cf1,
                      float* __restrict__ Cl0, float* __restrict__ Cl1,
                      int F0, int F1) {
  __shared__ float As[32][129];
  __shared__ float Bs[32][97];
  const int mmod = blockIdx.y;
  const float* A  = mmod ? A1 : A0;
  const float* Bt = mmod ? Bt1 : Bt0;
  const float* Bh = mmod ? Bh1 : Bh0;
  float* Cf = mmod ? Cf1 : Cf0;
  float* Cl = mmod ? Cl1 : Cl0;
  const int F = mmod ? F1 : F0;

  const int row0 = blockIdx.x * 128;
  const int tid = threadIdx.x;
  const int tx = tid & 15, ty = tid >> 4;
  const int lr = tid >> 1;            // load row 0..127
  const int lk = (tid & 1) * 16;      // load k offset
  const int gr_l = row0 + lr;
  const bool rok = gr_l < NITEMS;
  const float* Arow = A + (size_t)gr_l * F + lk;

  float4 a4[4];
  float bb[12];
  const float4 z4 = make_float4(0.f, 0.f, 0.f, 0.f);
#pragma unroll
  for (int i = 0; i < 4; i++) a4[i] = rok ? __ldg((const float4*)(Arow + 4 * i)) : z4;
#pragma unroll
  for (int i = 0; i < 12; i++) {
    int idx = tid + 256 * i, kk = idx / 96, c = idx - kk * 96;
    bb[i] = (c < 64) ? __ldg(Bt + kk * 64 + c) : __ldg(Bh + kk * 32 + (c - 64));
  }

  float acc[8][6];
#pragma unroll
  for (int i = 0; i < 8; i++)
#pragma unroll
    for (int j = 0; j < 6; j++) acc[i][j] = 0.0f;

  for (int k0 = 0; k0 < F; k0 += 32) {
#pragma unroll
    for (int i = 0; i < 4; i++) {
      As[lk + 4 * i + 0][lr] = a4[i].x;
      As[lk + 4 * i + 1][lr] = a4[i].y;
      As[lk + 4 * i + 2][lr] = a4[i].z;
      As[lk + 4 * i + 3][lr] = a4[i].w;
    }
#pragma unroll
    for (int i = 0; i < 12; i++) {
      int idx = tid + 256 * i, kk = idx / 96, c = idx - kk * 96;
      Bs[kk][c] = bb[i];
    }
    __syncthreads();
    int kn = k0 + 32;
    if (kn < F) {
#pragma unroll
      for (int i = 0; i < 4; i++) a4[i] = rok ? __ldg((const float4*)(Arow + kn + 4 * i)) : z4;
#pragma unroll
      for (int i = 0; i < 12; i++) {
        int idx = tid + 256 * i, kk = idx / 96, c = idx - kk * 96;
        bb[i] = (c < 64) ? __ldg(Bt + (kn + kk) * 64 + c) : __ldg(Bh + (kn + kk) * 32 + (c - 64));
      }
    }
#pragma unroll 8
    for (int kk = 0; kk < 32; kk++) {
      float a[8], b[6];
#pragma unroll
      for (int i = 0; i < 8; i++) a[i] = As[kk][ty * 8 + i];
#pragma unroll
      for (int j = 0; j < 6; j++) b[j] = Bs[kk][tx * 6 + j];
#pragma unroll
      for (int i = 0; i < 8; i++)
#pragma unroll
        for (int j = 0; j < 6; j++) acc[i][j] = fmaf(a[i], b[j], acc[i][j]);
    }
    __syncthreads();
  }
#pragma unroll
  for (int i = 0; i < 8; i++) {
    int gr = row0 + ty * 8 + i;
    if (gr < NITEMS) {
#pragma unroll
      for (int j = 0; j < 6; j++) {
        int c = tx * 6 + j;
        if (c < 64) Cf[gr * 64 + c] = acc[i][j];
        else        Cl[gr * 32 + (c - 64)] = acc[i][j];
      }
    }
  }
}

// ---------------- gumbel softmax both modalities, warp per row ----------------
__global__ void gumbel_both_kernel(const float* __restrict__ lg0, const float* __restrict__ lg1,
                                   float* __restrict__ o0, float* __restrict__ o1, int rows,
                                   unsigned k00, unsigned k01, unsigned k10, unsigned k11) {
  int row = blockIdx.x * 8 + (threadIdx.x >> 5);
  if (row >= rows) return;
  const float* logits = blockIdx.y ? lg1 : lg0;
  float* out = blockIdx.y ? o1 : o0;
  unsigned k0 = blockIdx.y ? k10 : k00;
  unsigned k1 = blockIdx.y ? k11 : k01;
  int lane = threadIdx.x & 31;
  unsigned idx = (unsigned)row * 32u + (unsigned)lane;
  unsigned b0, b1;
  tf2x32(k0, k1, 0u, idx, &b0, &b1);
  unsigned bits = b0 ^ b1;
  float f = __uint_as_float((bits >> 9) | 0x3f800000u) - 1.0f;
  const float TINY = 1.1754943508222875e-38f;
  float u = fmaxf(TINY, f + TINY);
  float g = -logf(-logf(u));
  float z = (logits[row * 32 + lane] + g) * 5.0f;   // /tau, tau=0.2
  float mx = z;
#pragma unroll
  for (int s = 16; s; s >>= 1) mx = fmaxf(mx, __shfl_xor_sync(0xffffffffu, mx, s));
  float e = expf(z - mx);
  float sm = e;
#pragma unroll
  for (int s = 16; s; s >>= 1) sm += __shfl_xor_sync(0xffffffffu, sm, s);
  out[row * 32 + lane] = e / sm;
}

// ---------------- cge combine: cge = (concat(Gu,Gi) + e1 + e2)/3 ----------------
__global__ void cge_combine_kernel(const float* __restrict__ Gu, const float* __restrict__ Gi,
                                   const float* __restrict__ e1, const float* __restrict__ e2,
                                   float* __restrict__ cge) {
  int idx = blockIdx.x * 256 + threadIdx.x;
  if (idx >= NNODES * EK) return;
  float ego = (idx < NUSERS * EK) ? Gu[idx] : Gi[idx - NUSERS * EK];
  cge[idx] = (ego + e1[idx] + e2[idx]) * (1.0f / 3.0f);
}

// ---------------- lat[32,64] += ih^T @ icge, both modalities (lat pre-zeroed) ----------------
__global__ void lat_both_kernel(const float* __restrict__ w0, const float* __restrict__ w1,
                                const float* __restrict__ icge,
                                float* __restrict__ lat0, float* __restrict__ lat1, int chunk) {
  const float* w = blockIdx.y ? w1 : w0;
  float* lat = blockIdx.y ? lat1 : lat0;
  int lane = threadIdx.x & 31;
  int kg = threadIdx.x >> 5;  // 0..7
  int start = blockIdx.x * chunk;
  int end = min(start + chunk, NITEMS);
  float acc[8] = {0, 0, 0, 0, 0, 0, 0, 0};
  for (int it = start; it < end; ++it) {
    float wv = w[it * HH + lane];
    const float* cr = icge + it * EK + kg * 8;
#pragma unroll
    for (int j = 0; j < 8; j++) acc[j] = fmaf(wv, __ldg(cr + j), acc[j]);
  }
#pragma unroll
  for (int j = 0; j < 8; j++) atomicAdd(&lat[lane * EK + kg * 8 + j], acc[j]);
}

// ---------------- hyper apply, all 4 outputs in one launch ----------------
#define IBLK ((NITEMS * EK + 255) / 256)
#define UBLK ((NUSERS * EK + 255) / 256)
__global__ void hyper_apply_all(const float* __restrict__ ih0, const float* __restrict__ ih1,
                                const float* __restrict__ uh0, const float* __restrict__ uh1,
                                const float* __restrict__ lat0, const float* __restrict__ lat1,
                                float* __restrict__ outIV, float* __restrict__ outIT,
                                float* __restrict__ outUV, float* __restrict__ outUT) {
  __shared__ float sl[HH * EK];
  const float* lat = blockIdx.y ? lat1 : lat0;
  for (int t = threadIdx.x; t < HH * EK; t += 256) sl[t] = lat[t];
  __syncthreads();
  const float* w;
  float* out;
  int idx;
  if (blockIdx.x < IBLK) {
    w = blockIdx.y ? ih1 : ih0;
    out = blockIdx.y ? outIT : outIV;
    idx = blockIdx.x * 256 + threadIdx.x;
    if (idx >= NITEMS * EK) return;
  } else {
    w = blockIdx.y ? uh1 : uh0;
    out = blockIdx.y ? outUT : outUV;
    idx = (blockIdx.x - IBLK) * 256 + threadIdx.x;
    if (idx >= NUSERS * EK) return;
  }
  int r = idx >> 6, k = idx & 63;
  float s = 0.0f;
#pragma unroll
  for (int h = 0; h < HH; h++) s = fmaf(w[r * HH + h], sl[h * EK + k], s);
  out[idx] = s;
}

// ---------------- final: out = cge + l2n(m1a) + l2n(m1b) + 0.2*l2n(ghe) ----------------
__global__ void final_kernel(float* __restrict__ out, const float* __restrict__ cge,
                             const float* __restrict__ m1a, const float* __restrict__ m1b) {
  const int OI   = NUSERS * EK;
  const int OHVU = (NUSERS + NITEMS) * EK;
  const int OHVI = OHVU + NUSERS * EK;
  const int OHTU = OHVI + NITEMS * EK;
  const int OHTI = OHTU + NUSERS * EK;
  int row = blockIdx.x * 8 + (threadIdx.x >> 5);
  if (row >= NNODES) return;
  int lane = threadIdx.x & 31;
  const float* hv;
  const float* ht;
  float* dst;
  if (row < NUSERS) {
    hv = out + OHVU + row * EK; ht = out + OHTU + row * EK; dst = out + row * EK;
  } else {
    int ir = row - NUSERS;
    hv = out + OHVI + ir * EK;  ht = out + OHTI + ir * EK;  dst = out + OI + ir * EK;
  }
  int b = row * EK;
  float a0 = m1a[b + lane], a1 = m1a[b + lane + 32];
  float c0 = m1b[b + lane], c1 = m1b[b + lane + 32];
  float g0 = hv[lane] + ht[lane];
  float g1 = hv[lane + 32] + ht[lane + 32];
  float sa = a0 * a0 + a1 * a1;
  float sc = c0 * c0 + c1 * c1;
  float sg = g0 * g0 + g1 * g1;
#pragma unroll
  for (int s = 16; s; s >>= 1) {
    sa += __shfl_xor_sync(0xffffffffu, sa, s);
    sc += __shfl_xor_sync(0xffffffffu, sc, s);
    sg += __shfl_xor_sync(0xffffffffu, sg, s);
  }
  float ia = 1.0f / fmaxf(sqrtf(sa), 1e-12f);
  float ic = 1.0f / fmaxf(sqrtf(sc), 1e-12f);
  float ig = 0.2f / fmaxf(sqrtf(sg), 1e-12f);
  dst[lane]      = cge[b + lane]      + a0 * ia + c0 * ic + g0 * ig;
  dst[lane + 32] = cge[b + lane + 32] + a1 * ia + c1 * ic + g1 * ig;
}

// ================================================================================
extern "C" void kernel_launch(void* const* d_in, const int* in_sizes, int n_in,
                              void* d_out, int out_size) {
  const float* Gu       = (const float*)d_in[0];
  const float* Gi       = (const float*)d_in[1];
  const float* feat_v   = (const float*)d_in[2];
  const float* feat_t   = (const float*)d_in[3];
  const float* trs_v    = (const float*)d_in[4];
  const float* trs_t    = (const float*)d_in[5];
  const float* hyp_v    = (const float*)d_in[6];
  const float* hyp_t    = (const float*)d_in[7];
  const float* inv      = (const float*)d_in[8];
  const float* adj_vals = (const float*)d_in[9];
  const float* r_vals   = (const float*)d_in[10];
  const int*   adj_rows = (const int*)d_in[11];
  const int*   adj_cols = (const int*)d_in[12];
  const int*   r_rows   = (const int*)d_in[13];
  const int*   r_cols   = (const int*)d_in[14];
  float* out = (float*)d_out;
  int Fv = in_sizes[2] / NITEMS;
  int Ft = in_sizes[3] / NITEMS;

  float *p_itf, *p_ihl, *p_uhl, *p_ih, *p_uh, *p_e0, *p_e1, *p_e2, *p_m0, *p_m1, *p_lat;
  cudaGetSymbolAddress((void**)&p_itf, g_itf);
  cudaGetSymbolAddress((void**)&p_ihl, g_ihl);
  cudaGetSymbolAddress((void**)&p_uhl, g_uhl);
  cudaGetSymbolAddress((void**)&p_ih,  g_ih);
  cudaGetSymbolAddress((void**)&p_uh,  g_uh);
  cudaGetSymbolAddress((void**)&p_e0,  g_e0);
  cudaGetSymbolAddress((void**)&p_e1,  g_e1);
  cudaGetSymbolAddress((void**)&p_e2,  g_e2);
  cudaGetSymbolAddress((void**)&p_m0,  g_m0);
  cudaGetSymbolAddress((void**)&p_m1,  g_m1);
  cudaGetSymbolAddress((void**)&p_lat, g_lat);
  float* p_itfT = p_itf + NITEMS * EK;
  float* p_ihlT = p_ihl + NITEMS * HH;
  float* p_uhlT = p_uhl + NUSERS * HH;
  float* p_ihT  = p_ih + NITEMS * HH;
  float* p_uhT  = p_uh + NUSERS * HH;
  float* p_m0T  = p_m0 + NUSERS * EK;
  float* p_m1T  = p_m1 + NNODES * EK;
  float* p_latT = p_lat + HH * EK;

  // JAX threefry keys (host arithmetic; deterministic)
  uint32_t ki0[2], ki1[2], ku0[2], ku1[2];
  for (int m = 0; m < 2; m++) {
    uint32_t km0, km1;
    tf2x32(0u, 42u, 0u, (uint32_t)m, &km0, &km1);   // fold_in(key(42), m)
    tf2x32(km0, km1, 0u, 0u, &ki0[m], &ki1[m]);     // split -> k1 (i_hyper)
    tf2x32(km0, km1, 0u, 1u, &ku0[m], &ku1[m]);     // split -> k2 (u_hyper)
  }

  const size_t NB  = (size_t)NNODES * EK * sizeof(float);
  const size_t UB  = (size_t)NUSERS * EK * sizeof(float);
  const size_t UHB = (size_t)NUSERS * HH * sizeof(float);
  const int GADJ16 = (NNZADJ * 16 + 255) / 256;
  const int GR8    = (NNZR * 8 + 255) / 256;
  const int GR16   = (NNZR * 16 + 255) / 256;
  const int GN     = (NNODES * EK + 255) / 256;
  const int OHVU = (NUSERS + NITEMS) * EK;
  const int OHVI = OHVU + NUSERS * EK;
  const int OHTU = OHVI + NITEMS * EK;
  const int OHTI = OHTU + NUSERS * EK;

  // ---- all scratch zeroing up front ----
  cudaMemsetAsync(p_e1, 0, NB, 0);
  cudaMemsetAsync(p_e2, 0, NB, 0);
  cudaMemsetAsync(p_uhl, 0, 2 * UHB, 0);
  cudaMemsetAsync(p_m0, 0, 2 * UB, 0);
  cudaMemsetAsync(p_m1, 0, 2 * NB, 0);
  cudaMemsetAsync(p_lat, 0, 2 * HH * EK * sizeof(float), 0);

  // ---- both GEMMs in one launch ----
  gemm_both_kernel<<<dim3((NITEMS + 127) / 128, 2), 256>>>(
      feat_v, feat_t, trs_v, trs_t, hyp_v, hyp_t,
      p_itf, p_itfT, p_ihl, p_ihlT, Fv, Ft);

  // ---- cge chain ----
  spmm_cge1<<<GADJ16, 256>>>(adj_rows, adj_cols, adj_vals,
                             (const float4*)Gu, (const float4*)Gi, (float4*)p_e1, NNZADJ);
  spmm_kernel<16><<<GADJ16, 256>>>(adj_rows, adj_cols, adj_vals,
                                   (const float4*)p_e1, (float4*)p_e2, NNZADJ);
  cge_combine_kernel<<<GN, 256>>>(Gu, Gi, p_e1, p_e2, p_e0);

  // ---- gumbel (items) both modalities ----
  gumbel_both_kernel<<<dim3((NITEMS + 7) / 8, 2), 256>>>(
      p_ihl, p_ihlT, p_ih, p_ihT, NITEMS, ki0[0], ki1[0], ki0[1], ki1[1]);

  // ---- r-spmms, both modalities ----
  spmm_r_both<8><<<dim3(GR8, 2), 256>>>(r_rows, r_cols, r_vals,
                                        (const float4*)p_ihl, (const float4*)p_ihlT,
                                        (float4*)p_uhl, (float4*)p_uhlT, NNZR);
  gumbel_both_kernel<<<dim3((NUSERS + 7) / 8, 2), 256>>>(
      p_uhl, p_uhlT, p_uh, p_uhT, NUSERS, ku0[0], ku1[0], ku0[1], ku1[1]);
  spmm_r_both<16><<<dim3(GR16, 2), 256>>>(r_rows, r_cols, r_vals,
                                          (const float4*)p_itf, (const float4*)p_itfT,
                                          (float4*)p_m0, (float4*)p_m0T, NNZR);

  // ---- mge adj spmm, both modalities ----
  spmm_mge_both<<<dim3(GADJ16, 2), 256>>>(adj_rows, adj_cols, adj_vals,
                                          (const float4*)p_m0, (const float4*)p_m0T,
                                          (const float4*)p_itf, (const float4*)p_itfT,
                                          inv, (float4*)p_m1, (float4*)p_m1T, NNZADJ);

  // ---- hyper path ----
  lat_both_kernel<<<dim3(120, 2), 256>>>(p_ih, p_ihT, p_e0 + NUSERS * EK, p_lat, p_latT, 250);
  hyper_apply_all<<<dim3(IBLK + UBLK, 2), 256>>>(
      p_ih, p_ihT, p_uh, p_uhT, p_lat, p_latT,
      out + OHVI, out + OHTI, out + OHVU, out + OHTU);

  final_kernel<<<(NNODES + 7) / 8, 256>>>(out, p_e0, p_m1, p_m1T);
}

// round 6
// speedup vs baseline: 1.6281x; 1.0864x over previous
#include <cuda_runtime.h>
#include <stdint.h>

#define NUSERS 50000
#define NITEMS 30000
#define NNODES 80000
#define EK 64
#define HH 32
#define NNZADJ 2000000
#define NNZR 1000000

// ---------------- scratch (device globals; allocation is forbidden) ----------------
__device__ float g_itf[2][NITEMS * EK];
__device__ float g_ihl[2][NITEMS * HH];
__device__ float g_uhl[2][NUSERS * HH];
__device__ float g_ih[2][NITEMS * HH];
__device__ float g_uh[2][NUSERS * HH];
__device__ float g_e0[NNODES * EK];      // cge
__device__ float g_e1[NNODES * EK];
__device__ float g_e2[NNODES * EK];
__device__ float g_m0[2][NUSERS * EK];
__device__ float g_m1[2][NNODES * EK];
__device__ float g_lat[2][HH * EK];

// ---------------- threefry2x32 (JAX-compatible, 20 rounds) ----------------
__host__ __device__ __forceinline__ void tf2x32(uint32_t k0, uint32_t k1,
                                                uint32_t x0, uint32_t x1,
                                                uint32_t* o0, uint32_t* o1) {
  uint32_t ks2 = k0 ^ k1 ^ 0x1BD11BDAu;
  uint32_t v0 = x0 + k0, v1 = x1 + k1;
#define TFR(r) { v0 += v1; v1 = (v1 << (r)) | (v1 >> (32 - (r))); v1 ^= v0; }
  TFR(13) TFR(15) TFR(26) TFR(6)
  v0 += k1;  v1 += ks2 + 1u;
  TFR(17) TFR(29) TFR(16) TFR(24)
  v0 += ks2; v1 += k0 + 2u;
  TFR(13) TFR(15) TFR(26) TFR(6)
  v0 += k0;  v1 += k1 + 3u;
  TFR(17) TFR(29) TFR(16) TFR(24)
  v0 += k1;  v1 += ks2 + 4u;
  TFR(13) TFR(15) TFR(26) TFR(6)
  v0 += ks2; v1 += k0 + 5u;
#undef TFR
  *o0 = v0; *o1 = v1;
}

// ---------------- vector atomic add ----------------
__device__ __forceinline__ void red_add_f4(float4* p, float4 v) {
  asm volatile("red.global.add.v4.f32 [%0], {%1,%2,%3,%4};"
               :: "l"(p), "f"(v.x), "f"(v.y), "f"(v.z), "f"(v.w) : "memory");
}

// ---------------- tf32 split + mma helpers ----------------
__device__ __forceinline__ void tf32split(float x, uint32_t& hi, uint32_t& lo) {
  uint32_t h;
  asm("cvt.rna.tf32.f32 %0, %1;" : "=r"(h) : "f"(x));
  float r = x - __uint_as_float(h);
  uint32_t l;
  asm("cvt.rna.tf32.f32 %0, %1;" : "=r"(l) : "f"(r));
  hi = h; lo = l;
}

__device__ __forceinline__ void mma8(float* c, const uint32_t* a, const uint32_t* b) {
  asm volatile("mma.sync.aligned.m16n8k8.row.col.f32.tf32.tf32.f32 "
               "{%0,%1,%2,%3}, {%4,%5,%6,%7}, {%8,%9}, {%0,%1,%2,%3};"
               : "+f"(c[0]), "+f"(c[1]), "+f"(c[2]), "+f"(c[3])
               : "r"(a[0]), "r"(a[1]), "r"(a[2]), "r"(a[3]), "r"(b[0]), "r"(b[1]));
}

// ---------------- SpMM: (edge,col4)-per-thread (coalesced), y pre-zeroed ----------------
template <int C4>
__global__ void spmm_kernel(const int* __restrict__ rows, const int* __restrict__ cols,
                            const float* __restrict__ vals, const float4* __restrict__ x,
                            float4* __restrict__ y, int nnz) {
  int idx = blockIdx.x * 256 + threadIdx.x;
  if (idx >= nnz * C4) return;
  int e = idx / C4;
  int c = idx - e * C4;
  int r = __ldg(rows + e), cl = __ldg(cols + e);
  float v = __ldg(vals + e);
  float4 xv = __ldg(x + (size_t)cl * C4 + c);
  red_add_f4(y + (size_t)r * C4 + c, make_float4(v * xv.x, v * xv.y, v * xv.z, v * xv.w));
}

// both-modality r-spmm: blockIdx.y selects modality
template <int C4>
__global__ void spmm_r_both(const int* __restrict__ rows, const int* __restrict__ cols,
                            const float* __restrict__ vals,
                            const float4* __restrict__ x0, const float4* __restrict__ x1,
                            float4* __restrict__ y0, float4* __restrict__ y1, int nnz) {
  int idx = blockIdx.x * 256 + threadIdx.x;
  if (idx >= nnz * C4) return;
  const float4* x = blockIdx.y ? x1 : x0;
  float4* y = blockIdx.y ? y1 : y0;
  int e = idx / C4;
  int c = idx - e * C4;
  int r = __ldg(rows + e), cl = __ldg(cols + e);
  float v = __ldg(vals + e);
  float4 xv = __ldg(x + (size_t)cl * C4 + c);
  red_add_f4(y + (size_t)r * C4 + c, make_float4(v * xv.x, v * xv.y, v * xv.z, v * xv.w));
}

// first cge spmm: gather virtually from concat(Gu, Gi)
__global__ void spmm_cge1(const int* __restrict__ rows, const int* __restrict__ cols,
                          const float* __restrict__ vals, const float4* __restrict__ Gu,
                          const float4* __restrict__ Gi, float4* __restrict__ y, int nnz) {
  int idx = blockIdx.x * 256 + threadIdx.x;
  if (idx >= nnz * 16) return;
  int e = idx >> 4;
  int c = idx & 15;
  int r = __ldg(rows + e), cl = __ldg(cols + e);
  float v = __ldg(vals + e);
  const float4* xr = (cl < NUSERS) ? Gu + (size_t)cl * 16 : Gi + (size_t)(cl - NUSERS) * 16;
  float4 xv = __ldg(xr + c);
  red_add_f4(y + (size_t)r * 16 + c, make_float4(v * xv.x, v * xv.y, v * xv.z, v * xv.w));
}

// mge adj spmm, both modalities; gathers from (m0users*inv | itf)
__global__ void spmm_mge_both(const int* __restrict__ rows, const int* __restrict__ cols,
                              const float* __restrict__ vals,
                              const float4* __restrict__ m0A, const float4* __restrict__ m0B,
                              const float4* __restrict__ itfA, const float4* __restrict__ itfB,
                              const float* __restrict__ inv,
                              float4* __restrict__ y0, float4* __restrict__ y1, int nnz) {
  int idx = blockIdx.x * 256 + threadIdx.x;
  if (idx >= nnz * 16) return;
  const float4* m0  = blockIdx.y ? m0B : m0A;
  const float4* itf = blockIdx.y ? itfB : itfA;
  float4* y = blockIdx.y ? y1 : y0;
  int e = idx >> 4;
  int c = idx & 15;
  int r = __ldg(rows + e), cl = __ldg(cols + e);
  float v = __ldg(vals + e);
  const float4* xr;
  if (cl < NUSERS) { xr = m0 + (size_t)cl * 16; v *= __ldg(inv + cl); }
  else             { xr = itf + (size_t)(cl - NUSERS) * 16; }
  float4 xv = __ldg(xr + c);
  red_add_f4(y + (size_t)r * 16 + c, make_float4(v * xv.x, v * xv.y, v * xv.z, v * xv.w));
}

// ---------------- fused GEMM both modalities: 3xTF32 tensor-core path ----------------
// blockIdx.y: 0 = visual, 1 = text. Cf = A@Bt [64 cols], Cl = A@Bh [32 cols].
// Block 128x96, 8 warps as 4(row)x2(col); warp tile 32x48 = 2 m16 x 6 n8.
__global__ __launch_bounds__(256, 2)
void gemm_both_kernel(const float* __restrict__ A0, const float* __restrict__ A1,
                      const float* __restrict__ Bt0, const float* __restrict__ Bt1,
                      const float* __restrict__ Bh0, const float* __restrict__ Bh1,
                      float* __restrict__ Cf0, float* __restrict__ Cf1,
                      float* __restrict__ Cl0, float* __restrict__ Cl1,
                      int F0, int F1) {
  __shared__ float As[32][129];   // As[k][row]
  __shared__ float Bs[32][97];    // Bs[k][col]
  const int mmod = blockIdx.y;
  const float* A  = mmod ? A1 : A0;
  const float* Bt = mmod ? Bt1 : Bt0;
  const float* Bh = mmod ? Bh1 : Bh0;
  float* Cf = mmod ? Cf1 : Cf0;
  float* Cl = mmod ? Cl1 : Cl0;
  const int F = mmod ? F1 : F0;

  const int row0 = blockIdx.x * 128;
  const int tid = threadIdx.x;
  const int wid = tid >> 5, lane = tid & 31;
  const int wr = wid >> 1, wc = wid & 1;
  const int qid = lane >> 2, qtid = lane & 3;

  // global->reg prefetch (same staging as round 5)
  const int lr = tid >> 1;            // load row 0..127
  const int lk = (tid & 1) * 16;      // load k offset
  const int gr_l = row0 + lr;
  const bool rok = gr_l < NITEMS;
  const float* Arow = A + (size_t)gr_l * F + lk;

  float4 a4[4];
  float bb[12];
  const float4 z4 = make_float4(0.f, 0.f, 0.f, 0.f);
#pragma unroll
  for (int i = 0; i < 4; i++) a4[i] = rok ? __ldg((const float4*)(Arow + 4 * i)) : z4;
#pragma unroll
  for (int i = 0; i < 12; i++) {
    int idx = tid + 256 * i, kk = idx / 96, c = idx - kk * 96;
    bb[i] = (c < 64) ? __ldg(Bt + kk * 64 + c) : __ldg(Bh + kk * 32 + (c - 64));
  }

  float acc[2][6][4];
#pragma unroll
  for (int mt = 0; mt < 2; mt++)
#pragma unroll
    for (int nt = 0; nt < 6; nt++)
#pragma unroll
      for (int j = 0; j < 4; j++) acc[mt][nt][j] = 0.0f;

  for (int k0 = 0; k0 < F; k0 += 32) {
#pragma unroll
    for (int i = 0; i < 4; i++) {
      As[lk + 4 * i + 0][lr] = a4[i].x;
      As[lk + 4 * i + 1][lr] = a4[i].y;
      As[lk + 4 * i + 2][lr] = a4[i].z;
      As[lk + 4 * i + 3][lr] = a4[i].w;
    }
#pragma unroll
    for (int i = 0; i < 12; i++) {
      int idx = tid + 256 * i, kk = idx / 96, c = idx - kk * 96;
      Bs[kk][c] = bb[i];
    }
    __syncthreads();
    int kn = k0 + 32;
    if (kn < F) {
#pragma unroll
      for (int i = 0; i < 4; i++) a4[i] = rok ? __ldg((const float4*)(Arow + kn + 4 * i)) : z4;
#pragma unroll
      for (int i = 0; i < 12; i++) {
        int idx = tid + 256 * i, kk = idx / 96, c = idx - kk * 96;
        bb[i] = (c < 64) ? __ldg(Bt + (kn + kk) * 64 + c) : __ldg(Bh + (kn + kk) * 32 + (c - 64));
      }
    }
#pragma unroll
    for (int ks = 0; ks < 4; ks++) {
      const int kb = ks * 8;
      uint32_t ahi[2][4], alo[2][4];
#pragma unroll
      for (int mt = 0; mt < 2; mt++) {
        int ar = wr * 32 + mt * 16 + qid;
        tf32split(As[kb + qtid][ar],         ahi[mt][0], alo[mt][0]);
        tf32split(As[kb + qtid][ar + 8],     ahi[mt][1], alo[mt][1]);
        tf32split(As[kb + qtid + 4][ar],     ahi[mt][2], alo[mt][2]);
        tf32split(As[kb + qtid + 4][ar + 8], ahi[mt][3], alo[mt][3]);
      }
#pragma unroll
      for (int nt = 0; nt < 6; nt++) {
        int bn = wc * 48 + nt * 8 + qid;
        uint32_t bh[2], bl[2];
        tf32split(Bs[kb + qtid][bn],     bh[0], bl[0]);
        tf32split(Bs[kb + qtid + 4][bn], bh[1], bl[1]);
#pragma unroll
        for (int mt = 0; mt < 2; mt++) {
          mma8(acc[mt][nt], ahi[mt], bh);
          mma8(acc[mt][nt], ahi[mt], bl);
          mma8(acc[mt][nt], alo[mt], bh);
        }
      }
    }
    __syncthreads();
  }

  // epilogue: c0,c1 at row qid; c2,c3 at row qid+8; cols 2*qtid, 2*qtid+1
#pragma unroll
  for (int mt = 0; mt < 2; mt++) {
    int gr = row0 + wr * 32 + mt * 16 + qid;
#pragma unroll
    for (int nt = 0; nt < 6; nt++) {
      int cc = wc * 48 + nt * 8 + 2 * qtid;
      if (gr < NITEMS) {
        if (cc < 64) { Cf[gr * 64 + cc] = acc[mt][nt][0]; Cf[gr * 64 + cc + 1] = acc[mt][nt][1]; }
        else         { Cl[gr * 32 + cc - 64] = acc[mt][nt][0]; Cl[gr * 32 + cc - 63] = acc[mt][nt][1]; }
      }
      if (gr + 8 < NITEMS) {
        if (cc < 64) { Cf[(gr + 8) * 64 + cc] = acc[mt][nt][2]; Cf[(gr + 8) * 64 + cc + 1] = acc[mt][nt][3]; }
        else         { Cl[(gr + 8) * 32 + cc - 64] = acc[mt][nt][2]; Cl[(gr + 8) * 32 + cc - 63] = acc[mt][nt][3]; }
      }
    }
  }
}

// ---------------- gumbel softmax both modalities, warp per row ----------------
__global__ void gumbel_both_kernel(const float* __restrict__ lg0, const float* __restrict__ lg1,
                                   float* __restrict__ o0, float* __restrict__ o1, int rows,
                                   unsigned k00, unsigned k01, unsigned k10, unsigned k11) {
  int row = blockIdx.x * 8 + (threadIdx.x >> 5);
  if (row >= rows) return;
  const float* logits = blockIdx.y ? lg1 : lg0;
  float* out = blockIdx.y ? o1 : o0;
  unsigned k0 = blockIdx.y ? k10 : k00;
  unsigned k1 = blockIdx.y ? k11 : k01;
  int lane = threadIdx.x & 31;
  unsigned idx = (unsigned)row * 32u + (unsigned)lane;
  unsigned b0, b1;
  tf2x32(k0, k1, 0u, idx, &b0, &b1);
  unsigned bits = b0 ^ b1;
  float f = __uint_as_float((bits >> 9) | 0x3f800000u) - 1.0f;
  const float TINY = 1.1754943508222875e-38f;
  float u = fmaxf(TINY, f + TINY);
  float g = -logf(-logf(u));
  float z = (logits[row * 32 + lane] + g) * 5.0f;   // /tau, tau=0.2
  float mx = z;
#pragma unroll
  for (int s = 16; s; s >>= 1) mx = fmaxf(mx, __shfl_xor_sync(0xffffffffu, mx, s));
  float e = expf(z - mx);
  float sm = e;
#pragma unroll
  for (int s = 16; s; s >>= 1) sm += __shfl_xor_sync(0xffffffffu, sm, s);
  out[row * 32 + lane] = e / sm;
}

// ---------------- cge combine: cge = (concat(Gu,Gi) + e1 + e2)/3 ----------------
__global__ void cge_combine_kernel(const float* __restrict__ Gu, const float* __restrict__ Gi,
                                   const float* __restrict__ e1, const float* __restrict__ e2,
                                   float* __restrict__ cge) {
  int idx = blockIdx.x * 256 + threadIdx.x;
  if (idx >= NNODES * EK) return;
  float ego = (idx < NUSERS * EK) ? Gu[idx] : Gi[idx - NUSERS * EK];
  cge[idx] = (ego + e1[idx] + e2[idx]) * (1.0f / 3.0f);
}

// ---------------- lat[32,64] += ih^T @ icge, both modalities (lat pre-zeroed) ----------------
__global__ void lat_both_kernel(const float* __restrict__ w0, const float* __restrict__ w1,
                                const float* __restrict__ icge,
                                float* __restrict__ lat0, float* __restrict__ lat1, int chunk) {
  const float* w = blockIdx.y ? w1 : w0;
  float* lat = blockIdx.y ? lat1 : lat0;
  int lane = threadIdx.x & 31;
  int kg = threadIdx.x >> 5;  // 0..7
  int start = blockIdx.x * chunk;
  int end = min(start + chunk, NITEMS);
  float acc[8] = {0, 0, 0, 0, 0, 0, 0, 0};
  for (int it = start; it < end; ++it) {
    float wv = w[it * HH + lane];
    const float* cr = icge + it * EK + kg * 8;
#pragma unroll
    for (int j = 0; j < 8; j++) acc[j] = fmaf(wv, __ldg(cr + j), acc[j]);
  }
#pragma unroll
  for (int j = 0; j < 8; j++) atomicAdd(&lat[lane * EK + kg * 8 + j], acc[j]);
}

// ---------------- hyper apply, all 4 outputs in one launch ----------------
#define IBLK ((NITEMS * EK + 255) / 256)
#define UBLK ((NUSERS * EK + 255) / 256)
__global__ void hyper_apply_all(const float* __restrict__ ih0, const float* __restrict__ ih1,
                                const float* __restrict__ uh0, const float* __restrict__ uh1,
                                const float* __restrict__ lat0, const float* __restrict__ lat1,
                                float* __restrict__ outIV, float* __restrict__ outIT,
                                float* __restrict__ outUV, float* __restrict__ outUT) {
  __shared__ float sl[HH * EK];
  const float* lat = blockIdx.y ? lat1 : lat0;
  for (int t = threadIdx.x; t < HH * EK; t += 256) sl[t] = lat[t];
  __syncthreads();
  const float* w;
  float* out;
  int idx;
  if (blockIdx.x < IBLK) {
    w = blockIdx.y ? ih1 : ih0;
    out = blockIdx.y ? outIT : outIV;
    idx = blockIdx.x * 256 + threadIdx.x;
    if (idx >= NITEMS * EK) return;
  } else {
    w = blockIdx.y ? uh1 : uh0;
    out = blockIdx.y ? outUT : outUV;
    idx = (blockIdx.x - IBLK) * 256 + threadIdx.x;
    if (idx >= NUSERS * EK) return;
  }
  int r = idx >> 6, k = idx & 63;
  float s = 0.0f;
#pragma unroll
  for (int h = 0; h < HH; h++) s = fmaf(w[r * HH + h], sl[h * EK + k], s);
  out[idx] = s;
}

// ---------------- final: out = cge + l2n(m1a) + l2n(m1b) + 0.2*l2n(ghe) ----------------
__global__ void final_kernel(float* __restrict__ out, const float* __restrict__ cge,
                             const float* __restrict__ m1a, const float* __restrict__ m1b) {
  const int OI   = NUSERS * EK;
  const int OHVU = (NUSERS + NITEMS) * EK;
  const int OHVI = OHVU + NUSERS * EK;
  const int OHTU = OHVI + NITEMS * EK;
  const int OHTI = OHTU + NUSERS * EK;
  int row = blockIdx.x * 8 + (threadIdx.x >> 5);
  if (row >= NNODES) return;
  int lane = threadIdx.x & 31;
  const float* hv;
  const float* ht;
  float* dst;
  if (row < NUSERS) {
    hv = out + OHVU + row * EK; ht = out + OHTU + row * EK; dst = out + row * EK;
  } else {
    int ir = row - NUSERS;
    hv = out + OHVI + ir * EK;  ht = out + OHTI + ir * EK;  dst = out + OI + ir * EK;
  }
  int b = row * EK;
  float a0 = m1a[b + lane], a1 = m1a[b + lane + 32];
  float c0 = m1b[b + lane], c1 = m1b[b + lane + 32];
  float g0 = hv[lane] + ht[lane];
  float g1 = hv[lane + 32] + ht[lane + 32];
  float sa = a0 * a0 + a1 * a1;
  float sc = c0 * c0 + c1 * c1;
  float sg = g0 * g0 + g1 * g1;
#pragma unroll
  for (int s = 16; s; s >>= 1) {
    sa += __shfl_xor_sync(0xffffffffu, sa, s);
    sc += __shfl_xor_sync(0xffffffffu, sc, s);
    sg += __shfl_xor_sync(0xffffffffu, sg, s);
  }
  float ia = 1.0f / fmaxf(sqrtf(sa), 1e-12f);
  float ic = 1.0f / fmaxf(sqrtf(sc), 1e-12f);
  float ig = 0.2f / fmaxf(sqrtf(sg), 1e-12f);
  dst[lane]      = cge[b + lane]      + a0 * ia + c0 * ic + g0 * ig;
  dst[lane + 32] = cge[b + lane + 32] + a1 * ia + c1 * ic + g1 * ig;
}

// ================================================================================
extern "C" void kernel_launch(void* const* d_in, const int* in_sizes, int n_in,
                              void* d_out, int out_size) {
  const float* Gu       = (const float*)d_in[0];
  const float* Gi       = (const float*)d_in[1];
  const float* feat_v   = (const float*)d_in[2];
  const float* feat_t   = (const float*)d_in[3];
  const float* trs_v    = (const float*)d_in[4];
  const float* trs_t    = (const float*)d_in[5];
  const float* hyp_v    = (const float*)d_in[6];
  const float* hyp_t    = (const float*)d_in[7];
  const float* inv      = (const float*)d_in[8];
  const float* adj_vals = (const float*)d_in[9];
  const float* r_vals   = (const float*)d_in[10];
  const int*   adj_rows = (const int*)d_in[11];
  const int*   adj_cols = (const int*)d_in[12];
  const int*   r_rows   = (const int*)d_in[13];
  const int*   r_cols   = (const int*)d_in[14];
  float* out = (float*)d_out;
  int Fv = in_sizes[2] / NITEMS;
  int Ft = in_sizes[3] / NITEMS;

  float *p_itf, *p_ihl, *p_uhl, *p_ih, *p_uh, *p_e0, *p_e1, *p_e2, *p_m0, *p_m1, *p_lat;
  cudaGetSymbolAddress((void**)&p_itf, g_itf);
  cudaGetSymbolAddress((void**)&p_ihl, g_ihl);
  cudaGetSymbolAddress((void**)&p_uhl, g_uhl);
  cudaGetSymbolAddress((void**)&p_ih,  g_ih);
  cudaGetSymbolAddress((void**)&p_uh,  g_uh);
  cudaGetSymbolAddress((void**)&p_e0,  g_e0);
  cudaGetSymbolAddress((void**)&p_e1,  g_e1);
  cudaGetSymbolAddress((void**)&p_e2,  g_e2);
  cudaGetSymbolAddress((void**)&p_m0,  g_m0);
  cudaGetSymbolAddress((void**)&p_m1,  g_m1);
  cudaGetSymbolAddress((void**)&p_lat, g_lat);
  float* p_itfT = p_itf + NITEMS * EK;
  float* p_ihlT = p_ihl + NITEMS * HH;
  float* p_uhlT = p_uhl + NUSERS * HH;
  float* p_ihT  = p_ih + NITEMS * HH;
  float* p_uhT  = p_uh + NUSERS * HH;
  float* p_m0T  = p_m0 + NUSERS * EK;
  float* p_m1T  = p_m1 + NNODES * EK;
  float* p_latT = p_lat + HH * EK;

  // JAX threefry keys (host arithmetic; deterministic)
  uint32_t ki0[2], ki1[2], ku0[2], ku1[2];
  for (int m = 0; m < 2; m++) {
    uint32_t km0, km1;
    tf2x32(0u, 42u, 0u, (uint32_t)m, &km0, &km1);   // fold_in(key(42), m)
    tf2x32(km0, km1, 0u, 0u, &ki0[m], &ki1[m]);     // split -> k1 (i_hyper)
    tf2x32(km0, km1, 0u, 1u, &ku0[m], &ku1[m]);     // split -> k2 (u_hyper)
  }

  const size_t NB  = (size_t)NNODES * EK * sizeof(float);
  const size_t UB  = (size_t)NUSERS * EK * sizeof(float);
  const size_t UHB = (size_t)NUSERS * HH * sizeof(float);
  const int GADJ16 = (NNZADJ * 16 + 255) / 256;
  const int GR8    = (NNZR * 8 + 255) / 256;
  const int GR16   = (NNZR * 16 + 255) / 256;
  const int GN     = (NNODES * EK + 255) / 256;
  const int OHVU = (NUSERS + NITEMS) * EK;
  const int OHVI = OHVU + NUSERS * EK;
  const int OHTU = OHVI + NITEMS * EK;
  const int OHTI = OHTU + NUSERS * EK;

  // ---- all scratch zeroing up front ----
  cudaMemsetAsync(p_e1, 0, NB, 0);
  cudaMemsetAsync(p_e2, 0, NB, 0);
  cudaMemsetAsync(p_uhl, 0, 2 * UHB, 0);
  cudaMemsetAsync(p_m0, 0, 2 * UB, 0);
  cudaMemsetAsync(p_m1, 0, 2 * NB, 0);
  cudaMemsetAsync(p_lat, 0, 2 * HH * EK * sizeof(float), 0);

  // ---- both GEMMs in one launch (3xTF32 tensor cores) ----
  gemm_both_kernel<<<dim3((NITEMS + 127) / 128, 2), 256>>>(
      feat_v, feat_t, trs_v, trs_t, hyp_v, hyp_t,
      p_itf, p_itfT, p_ihl, p_ihlT, Fv, Ft);

  // ---- cge chain ----
  spmm_cge1<<<GADJ16, 256>>>(adj_rows, adj_cols, adj_vals,
                             (const float4*)Gu, (const float4*)Gi, (float4*)p_e1, NNZADJ);
  spmm_kernel<16><<<GADJ16, 256>>>(adj_rows, adj_cols, adj_vals,
                                   (const float4*)p_e1, (float4*)p_e2, NNZADJ);
  cge_combine_kernel<<<GN, 256>>>(Gu, Gi, p_e1, p_e2, p_e0);

  // ---- gumbel (items) both modalities ----
  gumbel_both_kernel<<<dim3((NITEMS + 7) / 8, 2), 256>>>(
      p_ihl, p_ihlT, p_ih, p_ihT, NITEMS, ki0[0], ki1[0], ki0[1], ki1[1]);

  // ---- r-spmms, both modalities ----
  spmm_r_both<8><<<dim3(GR8, 2), 256>>>(r_rows, r_cols, r_vals,
                                        (const float4*)p_ihl, (const float4*)p_ihlT,
                                        (float4*)p_uhl, (float4*)p_uhlT, NNZR);
  gumbel_both_kernel<<<dim3((NUSERS + 7) / 8, 2), 256>>>(
      p_uhl, p_uhlT, p_uh, p_uhT, NUSERS, ku0[0], ku1[0], ku0[1], ku1[1]);
  spmm_r_both<16><<<dim3(GR16, 2), 256>>>(r_rows, r_cols, r_vals,
                                          (const float4*)p_itf, (const float4*)p_itfT,
                                          (float4*)p_m0, (float4*)p_m0T, NNZR);

  // ---- mge adj spmm, both modalities ----
  spmm_mge_both<<<dim3(GADJ16, 2), 256>>>(adj_rows, adj_cols, adj_vals,
                                          (const float4*)p_m0, (const float4*)p_m0T,
                                          (const float4*)p_itf, (const float4*)p_itfT,
                                          inv, (float4*)p_m1, (float4*)p_m1T, NNZADJ);

  // ---- hyper path ----
  lat_both_kernel<<<dim3(120, 2), 256>>>(p_ih, p_ihT, p_e0 + NUSERS * EK, p_lat, p_latT, 250);
  hyper_apply_all<<<dim3(IBLK + UBLK, 2), 256>>>(
      p_ih, p_ihT, p_uh, p_uhT, p_lat, p_latT,
      out + OHVI, out + OHTI, out + OHVU, out + OHTU);

  final_kernel<<<(NNODES + 7) / 8, 256>>>(out, p_e0, p_m1, p_m1T);
}